// round 12
// baseline (speedup 1.0000x reference)
#include <cuda_runtime.h>
#include <math.h>

#define BB 4
#define SS 512
#define HH 768
#define DD 24
#define MM 96
#define RR (BB*SS)      // 2048
#define KX (3*HH)       // 2304
#define ZST 514         // padded transpose stride

typedef unsigned long long ull;

// ---------------- tf32 helpers ----------------
__device__ __forceinline__ unsigned cvt_tf32(float x) {
    unsigned r; asm("cvt.rna.tf32.f32 %0, %1;" : "=r"(r) : "f"(x)); return r;
}
__device__ __forceinline__ void mma1688(float* c, const unsigned* a, const unsigned* b) {
    asm("mma.sync.aligned.m16n8k8.row.col.f32.tf32.tf32.f32 "
        "{%0,%1,%2,%3}, {%4,%5,%6,%7}, {%8,%9}, {%0,%1,%2,%3};"
        : "+f"(c[0]), "+f"(c[1]), "+f"(c[2]), "+f"(c[3])
        : "r"(a[0]), "r"(a[1]), "r"(a[2]), "r"(a[3]), "r"(b[0]), "r"(b[1]));
}

// ---------------- scratch ----------------
__device__ __align__(16) float g_Zj[BB*SS*DD];
__device__ __align__(16) float g_Zi[BB*SS*DD];
__device__ __align__(16) float g_probs[BB*SS*SS];
__device__ __align__(16) float g_ctx[BB*SS*HH];
__device__ __align__(16) float g_mhid[RR*HH];

// ---------------- K1: Z projections ----------------
__global__ void proj_kernel(const float* __restrict__ Hj, const float* __restrict__ Hi,
                            const float* __restrict__ Wpj, const float* __restrict__ Wpi)
{
    int which = blockIdx.y;
    const float* Hsrc = which ? Hi : Hj;
    const float* W    = which ? Wpi : Wpj;
    float* Z          = which ? g_Zi : g_Zj;
    int row = blockIdx.x * 8 + threadIdx.y;
    int col = threadIdx.x;
    const float* h = Hsrc + (size_t)row * HH;
    float acc = 0.f;
    #pragma unroll 8
    for (int k = 0; k < HH; ++k)
        acc = fmaf(h[k], W[k*DD + col], acc);
    Z[row*DD + col] = acc;
}

// ---------------- K2: pairwise scores via tf32 tensor cores + softmax (unchanged, proven) ----------------
__global__ void __launch_bounds__(256) pairwise_kernel(
        const float* __restrict__ Ws1, const float* __restrict__ bs1,
        const float* __restrict__ ws2, const float* __restrict__ bs2p,
        const int*   __restrict__ mask)
{
    extern __shared__ float smem[];
    float*    sZiT  = smem;                       // DD*ZST (12336) transposed [d][q]
    unsigned* sBf   = (unsigned*)(smem + DD*ZST); // 72 frag-tiles * 64 words = 4608
    float*    sL2   = smem + DD*ZST + 4608;       // 2 x 512 partial logits
    float*    sBias = sL2 + 2*SS;                 // 96
    float*    sWs2  = sBias + MM;                 // 96
    float*    sZj   = sWs2 + MM;                  // 24
    float*    sRed  = sZj + DD;                   // 32

    int b = blockIdx.y, p = blockIdx.x;
    int tid = threadIdx.x;
    int lane = tid & 31, warp = tid >> 5;
    int lm = lane >> 2, lk = lane & 3;
    int warp_m = warp >> 1, warp_n = warp & 1;

    if (tid < DD) sZj[tid] = g_Zj[((size_t)b*SS + p)*DD + tid];
    if (tid >= 128 && tid < 128 + MM) sWs2[tid - 128] = ws2[tid - 128];
    __syncthreads();

    {
        const float4* src = (const float4*)(g_Zi + (size_t)b*SS*DD);
        for (int i = tid; i < SS*DD/4; i += 256) {
            float4 v = src[i];
            int q = (4*i) / DD, d0 = (4*i) % DD;
            sZiT[(d0+0)*ZST+q] = v.x;
            sZiT[(d0+1)*ZST+q] = v.y;
            sZiT[(d0+2)*ZST+q] = v.z;
            sZiT[(d0+3)*ZST+q] = v.w;
        }
    }
    {
        int ft0 = warp * 9;
        #pragma unroll
        for (int i = 0; i < 9; ++i) {
            int ft = ft0 + i;
            int kt = ft / 12, nt = ft - kt*12;
            int n  = nt*8 + lm;
            unsigned v[2];
            #pragma unroll
            for (int j = 0; j < 2; ++j) {
                int k = kt*8 + lk + j*4;
                float w;
                if (k < DD)
                    w = fmaf(sZj[k], Ws1[(2*DD + k)*MM + n], Ws1[(DD + k)*MM + n]);
                else
                    w = Ws1[(2*DD + k)*MM + n];
                v[j] = cvt_tf32(w);
            }
            *(uint2*)&sBf[ft*64 + lane*2] = make_uint2(v[0], v[1]);
        }
    }
    if (tid < MM) {
        float acc = bs1[tid];
        #pragma unroll
        for (int d = 0; d < DD; ++d)
            acc = fmaf(sZj[d], Ws1[d*MM + tid], acc);
        sBias[tid] = acc;
    }
    __syncthreads();

    float zjk[3][2];
    #pragma unroll
    for (int t = 0; t < 3; ++t) {
        zjk[t][0] = sZj[t*8 + lk];
        zjk[t][1] = sZj[t*8 + lk + 4];
    }
    float bb[6][2], ww[6][2];
    #pragma unroll
    for (int nt = 0; nt < 6; ++nt) {
        int c = warp_n*48 + nt*8 + lk*2;
        bb[nt][0] = sBias[c];  bb[nt][1] = sBias[c+1];
        ww[nt][0] = sWs2[c];   ww[nt][1] = sWs2[c+1];
    }

    for (int mt = 0; mt < 8; ++mt) {
        int row = (warp_m*8 + mt)*16 + lm;
        float acc[6][4];
        #pragma unroll
        for (int nt = 0; nt < 6; ++nt)
            #pragma unroll
            for (int r = 0; r < 4; ++r) acc[nt][r] = 0.f;

        #pragma unroll
        for (int kt = 0; kt < 6; ++kt) {
            unsigned a[4];
            if (kt < 3) {
                int kd = kt*8 + lk;
                a[0] = cvt_tf32(sZiT[kd*ZST + row]);
                a[1] = cvt_tf32(sZiT[kd*ZST + row + 8]);
                a[2] = cvt_tf32(sZiT[(kd+4)*ZST + row]);
                a[3] = cvt_tf32(sZiT[(kd+4)*ZST + row + 8]);
            } else {
                int kd = (kt-3)*8 + lk;
                float z0 = zjk[kt-3][0], z1 = zjk[kt-3][1];
                a[0] = cvt_tf32(fabsf(z0 - sZiT[kd*ZST + row]));
                a[1] = cvt_tf32(fabsf(z0 - sZiT[kd*ZST + row + 8]));
                a[2] = cvt_tf32(fabsf(z1 - sZiT[(kd+4)*ZST + row]));
                a[3] = cvt_tf32(fabsf(z1 - sZiT[(kd+4)*ZST + row + 8]));
            }
            #pragma unroll
            for (int nt = 0; nt < 6; ++nt) {
                uint2 bf = *(const uint2*)&sBf[(kt*12 + warp_n*6 + nt)*64 + lane*2];
                unsigned bfr[2] = {bf.x, bf.y};
                mma1688(acc[nt], a, bfr);
            }
        }

        float s0 = 0.f, s8 = 0.f;
        #pragma unroll
        for (int nt = 0; nt < 6; ++nt) {
            s0 += fmaxf(acc[nt][0] + bb[nt][0], 0.f) * ww[nt][0]
                + fmaxf(acc[nt][1] + bb[nt][1], 0.f) * ww[nt][1];
            s8 += fmaxf(acc[nt][2] + bb[nt][0], 0.f) * ww[nt][0]
                + fmaxf(acc[nt][3] + bb[nt][1], 0.f) * ww[nt][1];
        }
        s0 += __shfl_xor_sync(0xffffffffu, s0, 1);
        s0 += __shfl_xor_sync(0xffffffffu, s0, 2);
        s8 += __shfl_xor_sync(0xffffffffu, s8, 1);
        s8 += __shfl_xor_sync(0xffffffffu, s8, 2);
        if (lk == 0) {
            sL2[warp_n*SS + row]     = s0;
            sL2[warp_n*SS + row + 8] = s8;
        }
    }
    __syncthreads();

    float bsc = bs2p[0];
    const int* mrow = mask + b*SS;
    for (int i = tid; i < SS; i += 256) {
        float lg = sL2[i] + sL2[SS + i] + bsc;
        if (mrow[i] == 0) lg = -3.0e38f;
        sL2[i] = lg;
    }
    __syncthreads();

    float v = -3.4e38f;
    for (int i = tid; i < SS; i += 256) v = fmaxf(v, sL2[i]);
    #pragma unroll
    for (int o = 16; o; o >>= 1) v = fmaxf(v, __shfl_xor_sync(0xffffffffu, v, o));
    if (lane == 0) sRed[warp] = v;
    __syncthreads();
    float gmax = sRed[0];
    #pragma unroll
    for (int w = 1; w < 8; ++w) gmax = fmaxf(gmax, sRed[w]);
    __syncthreads();

    float ls = 0.f;
    for (int i = tid; i < SS; i += 256) {
        float e = expf(sL2[i] - gmax);
        sL2[i] = e;
        ls += e;
    }
    #pragma unroll
    for (int o = 16; o; o >>= 1) ls += __shfl_xor_sync(0xffffffffu, ls, o);
    if (lane == 0) sRed[warp] = ls;
    __syncthreads();
    float gsum = 0.f;
    #pragma unroll
    for (int w = 0; w < 8; ++w) gsum += sRed[w];
    float inv = 1.f / gsum;

    float* prow = g_probs + ((size_t)b*SS + p)*SS;
    for (int i = tid; i < SS; i += 256) prow[i] = sL2[i] * inv;
}

// ---------------- tf32 tensor-core GEMM, 128x64 tile, 512 threads, BK=32, in-block split-K ----------------
// 16 warps: wg = warp>>3 picks k-half (ksteps 0-1 vs 2-3); within a wg, 8 warps form
// 4(m) x 2(n) grid of 32x32 warp tiles (proven LDS:MMA ratio: 2 LDS.128 + 4 LDS.64 per 8 MMAs).
// A: 32 frag-tiles (ks*8+mt) x 128 words; B: 32 frag-tiles (ks*8+nt) x 64 words; 2 tiles each per warp.
// After mainloop, wg1 dumps accumulators to smem (overlaying staging) and wg0 reduces + epilogue.
// MODE 0: plain; 1: relu(+bias); 2: alpha*(+bias). FUSE: A = [ctx | Hj | ctx*Hj].
template<int MODE, bool FUSE>
__global__ void __launch_bounds__(512) gemm_tf32(
        const float* __restrict__ A, const float* __restrict__ Bm, float* __restrict__ C,
        int K, int N, size_t strA, size_t strB, size_t strC,
        const float* __restrict__ bias, const float* __restrict__ alphap,
        const float* __restrict__ Ctx, const float* __restrict__ HjP)
{
    A  += (size_t)blockIdx.z * strA;
    Bm += (size_t)blockIdx.z * strB;
    C  += (size_t)blockIdx.z * strC;

    // 48KB: shA[2][4096] | shB[2][2048]; first 32KB reused as the reduction buffer
    __shared__ __align__(16) unsigned shMem[12288];
    unsigned (*shA)[4096] = (unsigned(*)[4096])shMem;
    unsigned (*shB)[2048] = (unsigned(*)[2048])(shMem + 8192);
    float* sRedu = (float*)shMem;   // 8192 floats, overlays shA

    int tid = threadIdx.x;
    int lane = tid & 31, warp = tid >> 5;          // warp 0..15
    int wg = warp >> 3, wsub = warp & 7;           // wg 0..1, wsub 0..7
    int warp_m = wsub >> 1, warp_n = wsub & 1;     // 4m x 2n
    int blockM = blockIdx.y * 128, blockN = blockIdx.x * 64;

    float acc[2][4][4];
    #pragma unroll
    for (int mi = 0; mi < 2; ++mi)
        #pragma unroll
        for (int ni = 0; ni < 4; ++ni)
            #pragma unroll
            for (int r = 0; r < 4; ++r) acc[mi][ni][r] = 0.f;

    int lm = lane >> 2, lk = lane & 3;

    // ---- A staging: 32 frag-tiles (ks*8 + mt); warp handles {warp*2, warp*2+1} ----
    auto stageA = [&](int kt, float ra[2][4]) {
        #pragma unroll
        for (int i = 0; i < 2; ++i) {
            int at = warp*2 + i;
            int ks = at >> 3, mt = at & 7;
            int m  = blockM + mt*16 + lm;
            int kg = kt + ks*8 + lk;
            if (FUSE) {
                int region = (kg >= 2*HH) ? 2 : ((kg >= HH) ? 1 : 0);
                int kh = kg - region*HH;
                size_t o00 = (size_t)m*HH + kh;
                size_t o10 = o00 + (size_t)8*HH;
                if (region == 0) {
                    ra[i][0] = Ctx[o00];     ra[i][1] = Ctx[o10];
                    ra[i][2] = Ctx[o00 + 4]; ra[i][3] = Ctx[o10 + 4];
                } else if (region == 1) {
                    ra[i][0] = HjP[o00];     ra[i][1] = HjP[o10];
                    ra[i][2] = HjP[o00 + 4]; ra[i][3] = HjP[o10 + 4];
                } else {
                    ra[i][0] = Ctx[o00]     * HjP[o00];
                    ra[i][1] = Ctx[o10]     * HjP[o10];
                    ra[i][2] = Ctx[o00 + 4] * HjP[o00 + 4];
                    ra[i][3] = Ctx[o10 + 4] * HjP[o10 + 4];
                }
            } else {
                const float* p0 = A + (size_t)m*K + kg;
                ra[i][0] = p0[0];
                ra[i][1] = p0[(size_t)8*K];
                ra[i][2] = p0[4];
                ra[i][3] = p0[(size_t)8*K + 4];
            }
        }
    };
    auto commitA = [&](const float ra[2][4], unsigned* dst) {
        #pragma unroll
        for (int i = 0; i < 2; ++i) {
            int at = warp*2 + i;
            uint4 v;
            v.x = cvt_tf32(ra[i][0]); v.y = cvt_tf32(ra[i][1]);
            v.z = cvt_tf32(ra[i][2]); v.w = cvt_tf32(ra[i][3]);
            *(uint4*)&dst[at*128 + lane*4] = v;
        }
    };
    // ---- B staging: 32 frag-tiles (ks*8 + nt); warp handles {warp*2, warp*2+1} ----
    auto stageB = [&](int kt, float rb[2][2]) {
        #pragma unroll
        for (int i = 0; i < 2; ++i) {
            int tb = warp*2 + i;
            int ks = tb >> 3, nt = tb & 7;
            int kg = kt + ks*8 + lk;
            int n  = blockN + nt*8 + lm;
            const float* p0 = Bm + (size_t)kg*N + n;
            rb[i][0] = p0[0];
            rb[i][1] = p0[(size_t)4*N];
        }
    };
    auto commitB = [&](const float rb[2][2], unsigned* dst) {
        #pragma unroll
        for (int i = 0; i < 2; ++i) {
            int tb = warp*2 + i;
            uint2 v;
            v.x = cvt_tf32(rb[i][0]); v.y = cvt_tf32(rb[i][1]);
            *(uint2*)&dst[tb*64 + lane*2] = v;
        }
    };

    // prologue
    {
        float ra[2][4], rb[2][2];
        stageA(0, ra); stageB(0, rb);
        commitA(ra, shA[0]); commitB(rb, shB[0]);
    }
    __syncthreads();

    int buf = 0;
    for (int kt = 0; kt < K; kt += 32) {
        float ra[2][4], rb[2][2];
        bool more = (kt + 32) < K;
        if (more) { stageA(kt + 32, ra); stageB(kt + 32, rb); }

        #pragma unroll
        for (int ksl = 0; ksl < 2; ++ksl) {
            int ks = wg*2 + ksl;
            unsigned afr[2][4], bfr[4][2];
            #pragma unroll
            for (int mi = 0; mi < 2; ++mi)
                *(uint4*)afr[mi] = *(const uint4*)&shA[buf][(ks*8 + warp_m*2 + mi)*128 + lane*4];
            #pragma unroll
            for (int ni = 0; ni < 4; ++ni)
                *(uint2*)bfr[ni] = *(const uint2*)&shB[buf][(ks*8 + warp_n*4 + ni)*64 + lane*2];
            #pragma unroll
            for (int mi = 0; mi < 2; ++mi)
                #pragma unroll
                for (int ni = 0; ni < 4; ++ni)
                    mma1688(acc[mi][ni], afr[mi], bfr[ni]);
        }

        if (more) { commitA(ra, shA[buf^1]); commitB(rb, shB[buf^1]); }
        __syncthreads();
        buf ^= 1;
    }

    // ---- in-block split-K reduction: wg1 -> smem, wg0 adds ----
    if (wg == 1) {
        #pragma unroll
        for (int mi = 0; mi < 2; ++mi)
            #pragma unroll
            for (int ni = 0; ni < 4; ++ni) {
                int t = (wsub*2 + mi)*4 + ni;
                *(float4*)&sRedu[t*128 + lane*4] = *(const float4*)acc[mi][ni];
            }
    }
    __syncthreads();
    if (wg == 0) {
        float al = (MODE == 2) ? *alphap : 1.f;
        #pragma unroll
        for (int mi = 0; mi < 2; ++mi) {
            int r0 = blockM + warp_m*32 + mi*16 + lm;
            #pragma unroll
            for (int ni = 0; ni < 4; ++ni) {
                int t = (wsub*2 + mi)*4 + ni;
                float4 part = *(const float4*)&sRedu[t*128 + lane*4];
                int c0 = blockN + warp_n*32 + ni*8 + lk*2;
                float b0 = 0.f, b1 = 0.f;
                if (MODE != 0) { float2 bv = *(const float2*)(bias + c0); b0 = bv.x; b1 = bv.y; }
                float v0 = acc[mi][ni][0] + part.x + b0;
                float v1 = acc[mi][ni][1] + part.y + b1;
                float v2 = acc[mi][ni][2] + part.z + b0;
                float v3 = acc[mi][ni][3] + part.w + b1;
                if (MODE == 1) {
                    v0 = fmaxf(v0, 0.f); v1 = fmaxf(v1, 0.f);
                    v2 = fmaxf(v2, 0.f); v3 = fmaxf(v3, 0.f);
                }
                if (MODE == 2) { v0 *= al; v1 *= al; v2 *= al; v3 *= al; }
                float2 lo; lo.x = v0; lo.y = v1;
                float2 hi; hi.x = v2; hi.y = v3;
                *(float2*)&C[(size_t)r0*N + c0]       = lo;
                *(float2*)&C[(size_t)(r0 + 8)*N + c0] = hi;
            }
        }
    }
}

// ---------------- launch ----------------
extern "C" void kernel_launch(void* const* d_in, const int* in_sizes, int n_in,
                              void* d_out, int out_size)
{
    const float* Hj   = (const float*)d_in[0];
    const float* Hi   = (const float*)d_in[1];
    const float* Wpj  = (const float*)d_in[2];
    const float* Wpi  = (const float*)d_in[3];
    const float* Ws1  = (const float*)d_in[4];
    const float* bs1  = (const float*)d_in[5];
    const float* ws2  = (const float*)d_in[6];
    const float* bs2  = (const float*)d_in[7];
    const float* Wv1  = (const float*)d_in[8];
    const float* bv1  = (const float*)d_in[9];
    const float* Wv2  = (const float*)d_in[10];
    const float* bv2  = (const float*)d_in[11];
    const float* alph = (const float*)d_in[12];
    const int*   amask= (const int*)d_in[13];
    float* out = (float*)d_out;

    float *pProbs, *pCtx, *pMhid;
    cudaGetSymbolAddress((void**)&pProbs, g_probs);
    cudaGetSymbolAddress((void**)&pCtx,   g_ctx);
    cudaGetSymbolAddress((void**)&pMhid,  g_mhid);

    // K1: projections
    proj_kernel<<<dim3(RR/8, 2), dim3(24, 8)>>>(Hj, Hi, Wpj, Wpi);

    // K2: pairwise scores on tensor cores + softmax
    const size_t smemPW = (size_t)(DD*ZST + 4608 + 2*SS + MM + MM + DD + 32) * sizeof(float);
    cudaFuncSetAttribute(pairwise_kernel, cudaFuncAttributeMaxDynamicSharedMemorySize, (int)smemPW);
    pairwise_kernel<<<dim3(SS, BB), 256, smemPW>>>(Ws1, bs1, ws2, bs2, amask);

    // K3: ctx = probs @ H_i   (per batch: M=512, K=512, N=768)
    gemm_tf32<0, false><<<dim3(HH/64, SS/128, BB), 512>>>(
        pProbs, Hi, pCtx, SS, HH,
        (size_t)SS*SS, (size_t)SS*HH, (size_t)SS*HH, nullptr, nullptr, nullptr, nullptr);

    // K4: mhid = relu(X @ Wv1 + bv1), X = [ctx|Hj|ctx*Hj] on the fly (M=2048, K=2304, N=768)
    gemm_tf32<1, true><<<dim3(HH/64, RR/128, 1), 512>>>(
        nullptr, Wv1, pMhid, KX, HH, 0, 0, 0, bv1, nullptr, pCtx, Hj);

    // K5: out = alpha * (mhid @ Wv2 + bv2)  (M=2048, K=768, N=768)
    gemm_tf32<2, false><<<dim3(HH/64, RR/128, 1), 512>>>(
        pMhid, Wv2, out, HH, HH, 0, 0, 0, bv2, alph, nullptr, nullptr);
}

// round 14
// speedup vs baseline: 1.0288x; 1.0288x over previous
#include <cuda_runtime.h>
#include <math.h>

#define BB 4
#define SS 512
#define HH 768
#define DD 24
#define MM 96
#define RR (BB*SS)      // 2048
#define KX (3*HH)       // 2304
#define ZST 514         // padded transpose stride

typedef unsigned long long ull;

// ---------------- tf32 helpers ----------------
__device__ __forceinline__ unsigned cvt_tf32(float x) {
    unsigned r; asm("cvt.rna.tf32.f32 %0, %1;" : "=r"(r) : "f"(x)); return r;
}
__device__ __forceinline__ void mma1688(float* c, const unsigned* a, const unsigned* b) {
    asm("mma.sync.aligned.m16n8k8.row.col.f32.tf32.tf32.f32 "
        "{%0,%1,%2,%3}, {%4,%5,%6,%7}, {%8,%9}, {%0,%1,%2,%3};"
        : "+f"(c[0]), "+f"(c[1]), "+f"(c[2]), "+f"(c[3])
        : "r"(a[0]), "r"(a[1]), "r"(a[2]), "r"(a[3]), "r"(b[0]), "r"(b[1]));
}

// ---------------- scratch ----------------
__device__ __align__(16) float g_Zj[BB*SS*DD];
__device__ __align__(16) float g_Zi[BB*SS*DD];
__device__ __align__(16) float g_probs[BB*SS*SS];
__device__ __align__(16) float g_ctx[BB*SS*HH];
__device__ __align__(16) float g_mhid[RR*HH];
__device__ __align__(16) float g_part[2*RR*HH];   // split-K partials

// ---------------- K1: Z projections ----------------
__global__ void proj_kernel(const float* __restrict__ Hj, const float* __restrict__ Hi,
                            const float* __restrict__ Wpj, const float* __restrict__ Wpi)
{
    int which = blockIdx.y;
    const float* Hsrc = which ? Hi : Hj;
    const float* W    = which ? Wpi : Wpj;
    float* Z          = which ? g_Zi : g_Zj;
    int row = blockIdx.x * 8 + threadIdx.y;
    int col = threadIdx.x;
    const float* h = Hsrc + (size_t)row * HH;
    float acc = 0.f;
    #pragma unroll 8
    for (int k = 0; k < HH; ++k)
        acc = fmaf(h[k], W[k*DD + col], acc);
    Z[row*DD + col] = acc;
}

// ---------------- K2: pairwise scores via tf32 tensor cores + softmax (proven) ----------------
__global__ void __launch_bounds__(256) pairwise_kernel(
        const float* __restrict__ Ws1, const float* __restrict__ bs1,
        const float* __restrict__ ws2, const float* __restrict__ bs2p,
        const int*   __restrict__ mask)
{
    extern __shared__ float smem[];
    float*    sZiT  = smem;                       // DD*ZST transposed [d][q]
    unsigned* sBf   = (unsigned*)(smem + DD*ZST); // 72 frag-tiles * 64 words
    float*    sL2   = smem + DD*ZST + 4608;       // 2 x 512 partial logits
    float*    sBias = sL2 + 2*SS;                 // 96
    float*    sWs2  = sBias + MM;                 // 96
    float*    sZj   = sWs2 + MM;                  // 24
    float*    sRed  = sZj + DD;                   // 32

    int b = blockIdx.y, p = blockIdx.x;
    int tid = threadIdx.x;
    int lane = tid & 31, warp = tid >> 5;
    int lm = lane >> 2, lk = lane & 3;
    int warp_m = warp >> 1, warp_n = warp & 1;

    if (tid < DD) sZj[tid] = g_Zj[((size_t)b*SS + p)*DD + tid];
    if (tid >= 128 && tid < 128 + MM) sWs2[tid - 128] = ws2[tid - 128];
    __syncthreads();

    {
        const float4* src = (const float4*)(g_Zi + (size_t)b*SS*DD);
        for (int i = tid; i < SS*DD/4; i += 256) {
            float4 v = src[i];
            int q = (4*i) / DD, d0 = (4*i) % DD;
            sZiT[(d0+0)*ZST+q] = v.x;
            sZiT[(d0+1)*ZST+q] = v.y;
            sZiT[(d0+2)*ZST+q] = v.z;
            sZiT[(d0+3)*ZST+q] = v.w;
        }
    }
    {
        int ft0 = warp * 9;
        #pragma unroll
        for (int i = 0; i < 9; ++i) {
            int ft = ft0 + i;
            int kt = ft / 12, nt = ft - kt*12;
            int n  = nt*8 + lm;
            unsigned v[2];
            #pragma unroll
            for (int j = 0; j < 2; ++j) {
                int k = kt*8 + lk + j*4;
                float w;
                if (k < DD)
                    w = fmaf(sZj[k], Ws1[(2*DD + k)*MM + n], Ws1[(DD + k)*MM + n]);
                else
                    w = Ws1[(2*DD + k)*MM + n];
                v[j] = cvt_tf32(w);
            }
            *(uint2*)&sBf[ft*64 + lane*2] = make_uint2(v[0], v[1]);
        }
    }
    if (tid < MM) {
        float acc = bs1[tid];
        #pragma unroll
        for (int d = 0; d < DD; ++d)
            acc = fmaf(sZj[d], Ws1[d*MM + tid], acc);
        sBias[tid] = acc;
    }
    __syncthreads();

    float zjk[3][2];
    #pragma unroll
    for (int t = 0; t < 3; ++t) {
        zjk[t][0] = sZj[t*8 + lk];
        zjk[t][1] = sZj[t*8 + lk + 4];
    }
    float bb[6][2], ww[6][2];
    #pragma unroll
    for (int nt = 0; nt < 6; ++nt) {
        int c = warp_n*48 + nt*8 + lk*2;
        bb[nt][0] = sBias[c];  bb[nt][1] = sBias[c+1];
        ww[nt][0] = sWs2[c];   ww[nt][1] = sWs2[c+1];
    }

    for (int mt = 0; mt < 8; ++mt) {
        int row = (warp_m*8 + mt)*16 + lm;
        float acc[6][4];
        #pragma unroll
        for (int nt = 0; nt < 6; ++nt)
            #pragma unroll
            for (int r = 0; r < 4; ++r) acc[nt][r] = 0.f;

        #pragma unroll
        for (int kt = 0; kt < 6; ++kt) {
            unsigned a[4];
            if (kt < 3) {
                int kd = kt*8 + lk;
                a[0] = cvt_tf32(sZiT[kd*ZST + row]);
                a[1] = cvt_tf32(sZiT[kd*ZST + row + 8]);
                a[2] = cvt_tf32(sZiT[(kd+4)*ZST + row]);
                a[3] = cvt_tf32(sZiT[(kd+4)*ZST + row + 8]);
            } else {
                int kd = (kt-3)*8 + lk;
                float z0 = zjk[kt-3][0], z1 = zjk[kt-3][1];
                a[0] = cvt_tf32(fabsf(z0 - sZiT[kd*ZST + row]));
                a[1] = cvt_tf32(fabsf(z0 - sZiT[kd*ZST + row + 8]));
                a[2] = cvt_tf32(fabsf(z1 - sZiT[(kd+4)*ZST + row]));
                a[3] = cvt_tf32(fabsf(z1 - sZiT[(kd+4)*ZST + row + 8]));
            }
            #pragma unroll
            for (int nt = 0; nt < 6; ++nt) {
                uint2 bf = *(const uint2*)&sBf[(kt*12 + warp_n*6 + nt)*64 + lane*2];
                unsigned bfr[2] = {bf.x, bf.y};
                mma1688(acc[nt], a, bfr);
            }
        }

        float s0 = 0.f, s8 = 0.f;
        #pragma unroll
        for (int nt = 0; nt < 6; ++nt) {
            s0 += fmaxf(acc[nt][0] + bb[nt][0], 0.f) * ww[nt][0]
                + fmaxf(acc[nt][1] + bb[nt][1], 0.f) * ww[nt][1];
            s8 += fmaxf(acc[nt][2] + bb[nt][0], 0.f) * ww[nt][0]
                + fmaxf(acc[nt][3] + bb[nt][1], 0.f) * ww[nt][1];
        }
        s0 += __shfl_xor_sync(0xffffffffu, s0, 1);
        s0 += __shfl_xor_sync(0xffffffffu, s0, 2);
        s8 += __shfl_xor_sync(0xffffffffu, s8, 1);
        s8 += __shfl_xor_sync(0xffffffffu, s8, 2);
        if (lk == 0) {
            sL2[warp_n*SS + row]     = s0;
            sL2[warp_n*SS + row + 8] = s8;
        }
    }
    __syncthreads();

    float bsc = bs2p[0];
    const int* mrow = mask + b*SS;
    for (int i = tid; i < SS; i += 256) {
        float lg = sL2[i] + sL2[SS + i] + bsc;
        if (mrow[i] == 0) lg = -3.0e38f;
        sL2[i] = lg;
    }
    __syncthreads();

    float v = -3.4e38f;
    for (int i = tid; i < SS; i += 256) v = fmaxf(v, sL2[i]);
    #pragma unroll
    for (int o = 16; o; o >>= 1) v = fmaxf(v, __shfl_xor_sync(0xffffffffu, v, o));
    if (lane == 0) sRed[warp] = v;
    __syncthreads();
    float gmax = sRed[0];
    #pragma unroll
    for (int w = 1; w < 8; ++w) gmax = fmaxf(gmax, sRed[w]);
    __syncthreads();

    float ls = 0.f;
    for (int i = tid; i < SS; i += 256) {
        float e = expf(sL2[i] - gmax);
        sL2[i] = e;
        ls += e;
    }
    #pragma unroll
    for (int o = 16; o; o >>= 1) ls += __shfl_xor_sync(0xffffffffu, ls, o);
    if (lane == 0) sRed[warp] = ls;
    __syncthreads();
    float gsum = 0.f;
    #pragma unroll
    for (int w = 0; w < 8; ++w) gsum += sRed[w];
    float inv = 1.f / gsum;

    float* prow = g_probs + ((size_t)b*SS + p)*SS;
    for (int i = tid; i < SS; i += 256) prow[i] = sL2[i] * inv;
}

// ---------------- gemm64: 64x64 tile, 256 threads, BK=32, in-block split-K (proven, for K3) ----------------
__global__ void __launch_bounds__(256) gemm64(
        const float* __restrict__ A, const float* __restrict__ Bm, float* __restrict__ C,
        int K, int N, size_t strA, size_t strB, size_t strC)
{
    A  += (size_t)blockIdx.z * strA;
    Bm += (size_t)blockIdx.z * strB;
    C  += (size_t)blockIdx.z * strC;

    __shared__ __align__(16) unsigned shMem[8192];
    unsigned (*shA)[2048] = (unsigned(*)[2048])shMem;
    unsigned (*shB)[2048] = (unsigned(*)[2048])(shMem + 4096);
    float* sRedu = (float*)shMem;

    int tid = threadIdx.x;
    int lane = tid & 31, warp = tid >> 5;
    int wg = warp >> 2, wsub = warp & 3;
    int warp_m = wsub >> 1, warp_n = wsub & 1;
    int blockM = blockIdx.y * 64, blockN = blockIdx.x * 64;

    float acc[2][4][4];
    #pragma unroll
    for (int mi = 0; mi < 2; ++mi)
        #pragma unroll
        for (int ni = 0; ni < 4; ++ni)
            #pragma unroll
            for (int r = 0; r < 4; ++r) acc[mi][ni][r] = 0.f;

    int lm = lane >> 2, lk = lane & 3;

    auto stageA = [&](int kt, float ra[2][4]) {
        #pragma unroll
        for (int i = 0; i < 2; ++i) {
            int at = warp*2 + i;
            int ks = at >> 2, mt = at & 3;
            int m  = blockM + mt*16 + lm;
            int kg = kt + ks*8 + lk;
            const float* p0 = A + (size_t)m*K + kg;
            ra[i][0] = p0[0];
            ra[i][1] = p0[(size_t)8*K];
            ra[i][2] = p0[4];
            ra[i][3] = p0[(size_t)8*K + 4];
        }
    };
    auto commitA = [&](const float ra[2][4], unsigned* dst) {
        #pragma unroll
        for (int i = 0; i < 2; ++i) {
            int at = warp*2 + i;
            uint4 v;
            v.x = cvt_tf32(ra[i][0]); v.y = cvt_tf32(ra[i][1]);
            v.z = cvt_tf32(ra[i][2]); v.w = cvt_tf32(ra[i][3]);
            *(uint4*)&dst[at*128 + lane*4] = v;
        }
    };
    auto stageB = [&](int kt, float rb[4][2]) {
        #pragma unroll
        for (int i = 0; i < 4; ++i) {
            int tb = warp*4 + i;
            int ks = tb >> 3, nt = tb & 7;
            int kg = kt + ks*8 + lk;
            int n  = blockN + nt*8 + lm;
            const float* p0 = Bm + (size_t)kg*N + n;
            rb[i][0] = p0[0];
            rb[i][1] = p0[(size_t)4*N];
        }
    };
    auto commitB = [&](const float rb[4][2], unsigned* dst) {
        #pragma unroll
        for (int i = 0; i < 4; ++i) {
            int tb = warp*4 + i;
            uint2 v;
            v.x = cvt_tf32(rb[i][0]); v.y = cvt_tf32(rb[i][1]);
            *(uint2*)&dst[tb*64 + lane*2] = v;
        }
    };

    {
        float ra[2][4], rb[4][2];
        stageA(0, ra); stageB(0, rb);
        commitA(ra, shA[0]); commitB(rb, shB[0]);
    }
    __syncthreads();

    int buf = 0;
    for (int kt = 0; kt < K; kt += 32) {
        float ra[2][4], rb[4][2];
        bool more = (kt + 32) < K;
        if (more) { stageA(kt + 32, ra); stageB(kt + 32, rb); }

        #pragma unroll
        for (int ksl = 0; ksl < 2; ++ksl) {
            int ks = wg*2 + ksl;
            unsigned afr[2][4], bfr[4][2];
            #pragma unroll
            for (int mi = 0; mi < 2; ++mi)
                *(uint4*)afr[mi] = *(const uint4*)&shA[buf][(ks*4 + warp_m*2 + mi)*128 + lane*4];
            #pragma unroll
            for (int ni = 0; ni < 4; ++ni)
                *(uint2*)bfr[ni] = *(const uint2*)&shB[buf][(ks*8 + warp_n*4 + ni)*64 + lane*2];
            #pragma unroll
            for (int mi = 0; mi < 2; ++mi)
                #pragma unroll
                for (int ni = 0; ni < 4; ++ni)
                    mma1688(acc[mi][ni], afr[mi], bfr[ni]);
        }

        if (more) { commitA(ra, shA[buf^1]); commitB(rb, shB[buf^1]); }
        __syncthreads();
        buf ^= 1;
    }

    if (wg == 1) {
        #pragma unroll
        for (int mi = 0; mi < 2; ++mi)
            #pragma unroll
            for (int ni = 0; ni < 4; ++ni) {
                int t = (wsub*2 + mi)*4 + ni;
                *(float4*)&sRedu[t*128 + lane*4] = *(const float4*)acc[mi][ni];
            }
    }
    __syncthreads();
    if (wg == 0) {
        #pragma unroll
        for (int mi = 0; mi < 2; ++mi) {
            int r0 = blockM + warp_m*32 + mi*16 + lm;
            #pragma unroll
            for (int ni = 0; ni < 4; ++ni) {
                int t = (wsub*2 + mi)*4 + ni;
                float4 part = *(const float4*)&sRedu[t*128 + lane*4];
                int c0 = blockN + warp_n*32 + ni*8 + lk*2;
                float2 lo; lo.x = acc[mi][ni][0] + part.x; lo.y = acc[mi][ni][1] + part.y;
                float2 hi; hi.x = acc[mi][ni][2] + part.z; hi.y = acc[mi][ni][3] + part.w;
                *(float2*)&C[(size_t)r0*N + c0]       = lo;
                *(float2*)&C[(size_t)(r0 + 8)*N + c0] = hi;
            }
        }
    }
}

// ---------------- gemm128sk: 128x64 tile, 512 threads, BK=32, in-block split-K + GLOBAL split-K ----------------
// blockIdx.z = k-slice (0/1): computes K range [z*kHalf, (z+1)*kHalf) into C + z*strC (raw partial).
// FUSE: A = [ctx | Hj | ctx*Hj] built on the fly.
template<bool FUSE>
__global__ void __launch_bounds__(512) gemm128sk(
        const float* __restrict__ A, const float* __restrict__ Bm, float* __restrict__ C,
        int K, int N, int kHalf, size_t strC,
        const float* __restrict__ Ctx, const float* __restrict__ HjP)
{
    int kOff = blockIdx.z * kHalf;
    C += (size_t)blockIdx.z * strC;

    __shared__ __align__(16) unsigned shMem[12288];
    unsigned (*shA)[4096] = (unsigned(*)[4096])shMem;
    unsigned (*shB)[2048] = (unsigned(*)[2048])(shMem + 8192);
    float* sRedu = (float*)shMem;

    int tid = threadIdx.x;
    int lane = tid & 31, warp = tid >> 5;
    int wg = warp >> 3, wsub = warp & 7;
    int warp_m = wsub >> 1, warp_n = wsub & 1;
    int blockM = blockIdx.y * 128, blockN = blockIdx.x * 64;

    float acc[2][4][4];
    #pragma unroll
    for (int mi = 0; mi < 2; ++mi)
        #pragma unroll
        for (int ni = 0; ni < 4; ++ni)
            #pragma unroll
            for (int r = 0; r < 4; ++r) acc[mi][ni][r] = 0.f;

    int lm = lane >> 2, lk = lane & 3;

    auto stageA = [&](int kt, float ra[2][4]) {    // kt is GLOBAL k
        #pragma unroll
        for (int i = 0; i < 2; ++i) {
            int at = warp*2 + i;
            int ks = at >> 3, mt = at & 7;
            int m  = blockM + mt*16 + lm;
            int kg = kt + ks*8 + lk;
            if (FUSE) {
                int region = (kg >= 2*HH) ? 2 : ((kg >= HH) ? 1 : 0);
                int kh = kg - region*HH;
                size_t o00 = (size_t)m*HH + kh;
                size_t o10 = o00 + (size_t)8*HH;
                if (region == 0) {
                    ra[i][0] = Ctx[o00];     ra[i][1] = Ctx[o10];
                    ra[i][2] = Ctx[o00 + 4]; ra[i][3] = Ctx[o10 + 4];
                } else if (region == 1) {
                    ra[i][0] = HjP[o00];     ra[i][1] = HjP[o10];
                    ra[i][2] = HjP[o00 + 4]; ra[i][3] = HjP[o10 + 4];
                } else {
                    ra[i][0] = Ctx[o00]     * HjP[o00];
                    ra[i][1] = Ctx[o10]     * HjP[o10];
                    ra[i][2] = Ctx[o00 + 4] * HjP[o00 + 4];
                    ra[i][3] = Ctx[o10 + 4] * HjP[o10 + 4];
                }
            } else {
                const float* p0 = A + (size_t)m*K + kg;
                ra[i][0] = p0[0];
                ra[i][1] = p0[(size_t)8*K];
                ra[i][2] = p0[4];
                ra[i][3] = p0[(size_t)8*K + 4];
            }
        }
    };
    auto commitA = [&](const float ra[2][4], unsigned* dst) {
        #pragma unroll
        for (int i = 0; i < 2; ++i) {
            int at = warp*2 + i;
            uint4 v;
            v.x = cvt_tf32(ra[i][0]); v.y = cvt_tf32(ra[i][1]);
            v.z = cvt_tf32(ra[i][2]); v.w = cvt_tf32(ra[i][3]);
            *(uint4*)&dst[at*128 + lane*4] = v;
        }
    };
    auto stageB = [&](int kt, float rb[2][2]) {    // kt is GLOBAL k
        #pragma unroll
        for (int i = 0; i < 2; ++i) {
            int tb = warp*2 + i;
            int ks = tb >> 3, nt = tb & 7;
            int kg = kt + ks*8 + lk;
            int n  = blockN + nt*8 + lm;
            const float* p0 = Bm + (size_t)kg*N + n;
            rb[i][0] = p0[0];
            rb[i][1] = p0[(size_t)4*N];
        }
    };
    auto commitB = [&](const float rb[2][2], unsigned* dst) {
        #pragma unroll
        for (int i = 0; i < 2; ++i) {
            int tb = warp*2 + i;
            uint2 v;
            v.x = cvt_tf32(rb[i][0]); v.y = cvt_tf32(rb[i][1]);
            *(uint2*)&dst[tb*64 + lane*2] = v;
        }
    };

    {
        float ra[2][4], rb[2][2];
        stageA(kOff, ra); stageB(kOff, rb);
        commitA(ra, shA[0]); commitB(rb, shB[0]);
    }
    __syncthreads();

    int buf = 0;
    int kEnd = kOff + kHalf;
    for (int kt = kOff; kt < kEnd; kt += 32) {
        float ra[2][4], rb[2][2];
        bool more = (kt + 32) < kEnd;
        if (more) { stageA(kt + 32, ra); stageB(kt + 32, rb); }

        #pragma unroll
        for (int ksl = 0; ksl < 2; ++ksl) {
            int ks = wg*2 + ksl;
            unsigned afr[2][4], bfr[4][2];
            #pragma unroll
            for (int mi = 0; mi < 2; ++mi)
                *(uint4*)afr[mi] = *(const uint4*)&shA[buf][(ks*8 + warp_m*2 + mi)*128 + lane*4];
            #pragma unroll
            for (int ni = 0; ni < 4; ++ni)
                *(uint2*)bfr[ni] = *(const uint2*)&shB[buf][(ks*8 + warp_n*4 + ni)*64 + lane*2];
            #pragma unroll
            for (int mi = 0; mi < 2; ++mi)
                #pragma unroll
                for (int ni = 0; ni < 4; ++ni)
                    mma1688(acc[mi][ni], afr[mi], bfr[ni]);
        }

        if (more) { commitA(ra, shA[buf^1]); commitB(rb, shB[buf^1]); }
        __syncthreads();
        buf ^= 1;
    }

    if (wg == 1) {
        #pragma unroll
        for (int mi = 0; mi < 2; ++mi)
            #pragma unroll
            for (int ni = 0; ni < 4; ++ni) {
                int t = (wsub*2 + mi)*4 + ni;
                *(float4*)&sRedu[t*128 + lane*4] = *(const float4*)acc[mi][ni];
            }
    }
    __syncthreads();
    if (wg == 0) {
        #pragma unroll
        for (int mi = 0; mi < 2; ++mi) {
            int r0 = blockM + warp_m*32 + mi*16 + lm;
            #pragma unroll
            for (int ni = 0; ni < 4; ++ni) {
                int t = (wsub*2 + mi)*4 + ni;
                float4 part = *(const float4*)&sRedu[t*128 + lane*4];
                int c0 = blockN + warp_n*32 + ni*8 + lk*2;
                float2 lo; lo.x = acc[mi][ni][0] + part.x; lo.y = acc[mi][ni][1] + part.y;
                float2 hi; hi.x = acc[mi][ni][2] + part.z; hi.y = acc[mi][ni][3] + part.w;
                *(float2*)&C[(size_t)r0*N + c0]       = lo;
                *(float2*)&C[(size_t)(r0 + 8)*N + c0] = hi;
            }
        }
    }
}

// ---------------- reduce: out = op(p0 + p1 + bias) ----------------
// MODE 1: relu; MODE 2: alpha*(.)
template<int MODE>
__global__ void __launch_bounds__(256) reduce_kernel(
        const float* __restrict__ p0, const float* __restrict__ p1,
        const float* __restrict__ bias, const float* __restrict__ alphap,
        float* __restrict__ out)
{
    int i = blockIdx.x * 256 + threadIdx.x;        // float4 index; RR*HH/4 total
    float4 a = ((const float4*)p0)[i];
    float4 b = ((const float4*)p1)[i];
    int col = (i*4) % HH;
    float4 bv = *(const float4*)&bias[col];
    float v0 = a.x + b.x + bv.x;
    float v1 = a.y + b.y + bv.y;
    float v2 = a.z + b.z + bv.z;
    float v3 = a.w + b.w + bv.w;
    if (MODE == 1) {
        v0 = fmaxf(v0, 0.f); v1 = fmaxf(v1, 0.f);
        v2 = fmaxf(v2, 0.f); v3 = fmaxf(v3, 0.f);
    } else {
        float al = *alphap;
        v0 *= al; v1 *= al; v2 *= al; v3 *= al;
    }
    float4 o; o.x = v0; o.y = v1; o.z = v2; o.w = v3;
    ((float4*)out)[i] = o;
}

// ---------------- launch ----------------
extern "C" void kernel_launch(void* const* d_in, const int* in_sizes, int n_in,
                              void* d_out, int out_size)
{
    const float* Hj   = (const float*)d_in[0];
    const float* Hi   = (const float*)d_in[1];
    const float* Wpj  = (const float*)d_in[2];
    const float* Wpi  = (const float*)d_in[3];
    const float* Ws1  = (const float*)d_in[4];
    const float* bs1  = (const float*)d_in[5];
    const float* ws2  = (const float*)d_in[6];
    const float* bs2  = (const float*)d_in[7];
    const float* Wv1  = (const float*)d_in[8];
    const float* bv1  = (const float*)d_in[9];
    const float* Wv2  = (const float*)d_in[10];
    const float* bv2  = (const float*)d_in[11];
    const float* alph = (const float*)d_in[12];
    const int*   amask= (const int*)d_in[13];
    float* out = (float*)d_out;

    float *pProbs, *pCtx, *pMhid, *pPart;
    cudaGetSymbolAddress((void**)&pProbs, g_probs);
    cudaGetSymbolAddress((void**)&pCtx,   g_ctx);
    cudaGetSymbolAddress((void**)&pMhid,  g_mhid);
    cudaGetSymbolAddress((void**)&pPart,  g_part);

    // K1: projections
    proj_kernel<<<dim3(RR/8, 2), dim3(24, 8)>>>(Hj, Hi, Wpj, Wpi);

    // K2: pairwise scores on tensor cores + softmax
    const size_t smemPW = (size_t)(DD*ZST + 4608 + 2*SS + MM + MM + DD + 32) * sizeof(float);
    cudaFuncSetAttribute(pairwise_kernel, cudaFuncAttributeMaxDynamicSharedMemorySize, (int)smemPW);
    pairwise_kernel<<<dim3(SS, BB), 256, smemPW>>>(Ws1, bs1, ws2, bs2, amask);

    // K3: ctx = probs @ H_i   (per batch: M=512, K=512, N=768) — proven 64x64 config
    gemm64<<<dim3(HH/64, SS/64, BB), 256>>>(
        pProbs, Hi, pCtx, SS, HH,
        (size_t)SS*SS, (size_t)SS*HH, (size_t)SS*HH);

    // K4: partials of X @ Wv1 (M=2048, K=2304 split 2x1152, N=768), then relu(+bv1) reduce
    gemm128sk<true><<<dim3(HH/64, RR/128, 2), 512>>>(
        nullptr, Wv1, pPart, KX, HH, KX/2, (size_t)RR*HH, pCtx, Hj);
    reduce_kernel<1><<<RR*HH/4/256, 256>>>(pPart, pPart + (size_t)RR*HH, bv1, nullptr, pMhid);

    // K5: partials of mhid @ Wv2 (M=2048, K=768 split 2x384, N=768), then alpha*(+bv2) reduce
    gemm128sk<false><<<dim3(HH/64, RR/128, 2), 512>>>(
        pMhid, Wv2, pPart, HH, HH, HH/2, (size_t)RR*HH, nullptr, nullptr);
    reduce_kernel<2><<<RR*HH/4/256, 256>>>(pPart, pPart + (size_t)RR*HH, bv2, alph, out);
}

// round 15
// speedup vs baseline: 1.4326x; 1.3925x over previous
#include <cuda_runtime.h>
#include <cuda_fp16.h>
#include <math.h>

#define BB 4
#define SS 512
#define HH 768
#define DD 24
#define MM 96
#define RR (BB*SS)      // 2048
#define KX (3*HH)       // 2304
#define ZST 514         // padded transpose stride

// ---------------- tf32 helpers (pairwise kernel) ----------------
__device__ __forceinline__ unsigned cvt_tf32(float x) {
    unsigned r; asm("cvt.rna.tf32.f32 %0, %1;" : "=r"(r) : "f"(x)); return r;
}
__device__ __forceinline__ void mma1688(float* c, const unsigned* a, const unsigned* b) {
    asm("mma.sync.aligned.m16n8k8.row.col.f32.tf32.tf32.f32 "
        "{%0,%1,%2,%3}, {%4,%5,%6,%7}, {%8,%9}, {%0,%1,%2,%3};"
        : "+f"(c[0]), "+f"(c[1]), "+f"(c[2]), "+f"(c[3])
        : "r"(a[0]), "r"(a[1]), "r"(a[2]), "r"(a[3]), "r"(b[0]), "r"(b[1]));
}

// ---------------- fp16 helpers (GEMMs) ----------------
__device__ __forceinline__ unsigned pack_h2(float lo, float hi) {
    __half2 h = __floats2half2_rn(lo, hi);
    return *(unsigned*)&h;
}
__device__ __forceinline__ void mma16816(float* c, const unsigned* a, const unsigned* b) {
    asm("mma.sync.aligned.m16n8k16.row.col.f32.f16.f16.f32 "
        "{%0,%1,%2,%3}, {%4,%5,%6,%7}, {%8,%9}, {%0,%1,%2,%3};"
        : "+f"(c[0]), "+f"(c[1]), "+f"(c[2]), "+f"(c[3])
        : "r"(a[0]), "r"(a[1]), "r"(a[2]), "r"(a[3]), "r"(b[0]), "r"(b[1]));
}

// ---------------- scratch ----------------
__device__ __align__(16) float g_Zj[BB*SS*DD];
__device__ __align__(16) float g_Zi[BB*SS*DD];
__device__ __align__(16) float g_probs[BB*SS*SS];
__device__ __align__(16) float g_ctx[BB*SS*HH];
__device__ __align__(16) float g_mhid[RR*HH];

// ---------------- K1: Z projections ----------------
__global__ void proj_kernel(const float* __restrict__ Hj, const float* __restrict__ Hi,
                            const float* __restrict__ Wpj, const float* __restrict__ Wpi)
{
    int which = blockIdx.y;
    const float* Hsrc = which ? Hi : Hj;
    const float* W    = which ? Wpi : Wpj;
    float* Z          = which ? g_Zi : g_Zj;
    int row = blockIdx.x * 8 + threadIdx.y;
    int col = threadIdx.x;
    const float* h = Hsrc + (size_t)row * HH;
    float acc = 0.f;
    #pragma unroll 8
    for (int k = 0; k < HH; ++k)
        acc = fmaf(h[k], W[k*DD + col], acc);
    Z[row*DD + col] = acc;
}

// ---------------- K2: pairwise scores via tf32 tensor cores + softmax (proven, unchanged) ----------------
__global__ void __launch_bounds__(256) pairwise_kernel(
        const float* __restrict__ Ws1, const float* __restrict__ bs1,
        const float* __restrict__ ws2, const float* __restrict__ bs2p,
        const int*   __restrict__ mask)
{
    extern __shared__ float smem[];
    float*    sZiT  = smem;                       // DD*ZST transposed [d][q]
    unsigned* sBf   = (unsigned*)(smem + DD*ZST); // 72 frag-tiles * 64 words
    float*    sL2   = smem + DD*ZST + 4608;       // 2 x 512 partial logits
    float*    sBias = sL2 + 2*SS;                 // 96
    float*    sWs2  = sBias + MM;                 // 96
    float*    sZj   = sWs2 + MM;                  // 24
    float*    sRed  = sZj + DD;                   // 32

    int b = blockIdx.y, p = blockIdx.x;
    int tid = threadIdx.x;
    int lane = tid & 31, warp = tid >> 5;
    int lm = lane >> 2, lk = lane & 3;
    int warp_m = warp >> 1, warp_n = warp & 1;

    if (tid < DD) sZj[tid] = g_Zj[((size_t)b*SS + p)*DD + tid];
    if (tid >= 128 && tid < 128 + MM) sWs2[tid - 128] = ws2[tid - 128];
    __syncthreads();

    {
        const float4* src = (const float4*)(g_Zi + (size_t)b*SS*DD);
        for (int i = tid; i < SS*DD/4; i += 256) {
            float4 v = src[i];
            int q = (4*i) / DD, d0 = (4*i) % DD;
            sZiT[(d0+0)*ZST+q] = v.x;
            sZiT[(d0+1)*ZST+q] = v.y;
            sZiT[(d0+2)*ZST+q] = v.z;
            sZiT[(d0+3)*ZST+q] = v.w;
        }
    }
    {
        int ft0 = warp * 9;
        #pragma unroll
        for (int i = 0; i < 9; ++i) {
            int ft = ft0 + i;
            int kt = ft / 12, nt = ft - kt*12;
            int n  = nt*8 + lm;
            unsigned v[2];
            #pragma unroll
            for (int j = 0; j < 2; ++j) {
                int k = kt*8 + lk + j*4;
                float w;
                if (k < DD)
                    w = fmaf(sZj[k], Ws1[(2*DD + k)*MM + n], Ws1[(DD + k)*MM + n]);
                else
                    w = Ws1[(2*DD + k)*MM + n];
                v[j] = cvt_tf32(w);
            }
            *(uint2*)&sBf[ft*64 + lane*2] = make_uint2(v[0], v[1]);
        }
    }
    if (tid < MM) {
        float acc = bs1[tid];
        #pragma unroll
        for (int d = 0; d < DD; ++d)
            acc = fmaf(sZj[d], Ws1[d*MM + tid], acc);
        sBias[tid] = acc;
    }
    __syncthreads();

    float zjk[3][2];
    #pragma unroll
    for (int t = 0; t < 3; ++t) {
        zjk[t][0] = sZj[t*8 + lk];
        zjk[t][1] = sZj[t*8 + lk + 4];
    }
    float bb[6][2], ww[6][2];
    #pragma unroll
    for (int nt = 0; nt < 6; ++nt) {
        int c = warp_n*48 + nt*8 + lk*2;
        bb[nt][0] = sBias[c];  bb[nt][1] = sBias[c+1];
        ww[nt][0] = sWs2[c];   ww[nt][1] = sWs2[c+1];
    }

    for (int mt = 0; mt < 8; ++mt) {
        int row = (warp_m*8 + mt)*16 + lm;
        float acc[6][4];
        #pragma unroll
        for (int nt = 0; nt < 6; ++nt)
            #pragma unroll
            for (int r = 0; r < 4; ++r) acc[nt][r] = 0.f;

        #pragma unroll
        for (int kt = 0; kt < 6; ++kt) {
            unsigned a[4];
            if (kt < 3) {
                int kd = kt*8 + lk;
                a[0] = cvt_tf32(sZiT[kd*ZST + row]);
                a[1] = cvt_tf32(sZiT[kd*ZST + row + 8]);
                a[2] = cvt_tf32(sZiT[(kd+4)*ZST + row]);
                a[3] = cvt_tf32(sZiT[(kd+4)*ZST + row + 8]);
            } else {
                int kd = (kt-3)*8 + lk;
                float z0 = zjk[kt-3][0], z1 = zjk[kt-3][1];
                a[0] = cvt_tf32(fabsf(z0 - sZiT[kd*ZST + row]));
                a[1] = cvt_tf32(fabsf(z0 - sZiT[kd*ZST + row + 8]));
                a[2] = cvt_tf32(fabsf(z1 - sZiT[(kd+4)*ZST + row]));
                a[3] = cvt_tf32(fabsf(z1 - sZiT[(kd+4)*ZST + row + 8]));
            }
            #pragma unroll
            for (int nt = 0; nt < 6; ++nt) {
                uint2 bf = *(const uint2*)&sBf[(kt*12 + warp_n*6 + nt)*64 + lane*2];
                unsigned bfr[2] = {bf.x, bf.y};
                mma1688(acc[nt], a, bfr);
            }
        }

        float s0 = 0.f, s8 = 0.f;
        #pragma unroll
        for (int nt = 0; nt < 6; ++nt) {
            s0 += fmaxf(acc[nt][0] + bb[nt][0], 0.f) * ww[nt][0]
                + fmaxf(acc[nt][1] + bb[nt][1], 0.f) * ww[nt][1];
            s8 += fmaxf(acc[nt][2] + bb[nt][0], 0.f) * ww[nt][0]
                + fmaxf(acc[nt][3] + bb[nt][1], 0.f) * ww[nt][1];
        }
        s0 += __shfl_xor_sync(0xffffffffu, s0, 1);
        s0 += __shfl_xor_sync(0xffffffffu, s0, 2);
        s8 += __shfl_xor_sync(0xffffffffu, s8, 1);
        s8 += __shfl_xor_sync(0xffffffffu, s8, 2);
        if (lk == 0) {
            sL2[warp_n*SS + row]     = s0;
            sL2[warp_n*SS + row + 8] = s8;
        }
    }
    __syncthreads();

    float bsc = bs2p[0];
    const int* mrow = mask + b*SS;
    for (int i = tid; i < SS; i += 256) {
        float lg = sL2[i] + sL2[SS + i] + bsc;
        if (mrow[i] == 0) lg = -3.0e38f;
        sL2[i] = lg;
    }
    __syncthreads();

    float v = -3.4e38f;
    for (int i = tid; i < SS; i += 256) v = fmaxf(v, sL2[i]);
    #pragma unroll
    for (int o = 16; o; o >>= 1) v = fmaxf(v, __shfl_xor_sync(0xffffffffu, v, o));
    if (lane == 0) sRed[warp] = v;
    __syncthreads();
    float gmax = sRed[0];
    #pragma unroll
    for (int w = 1; w < 8; ++w) gmax = fmaxf(gmax, sRed[w]);
    __syncthreads();

    float ls = 0.f;
    for (int i = tid; i < SS; i += 256) {
        float e = expf(sL2[i] - gmax);
        sL2[i] = e;
        ls += e;
    }
    #pragma unroll
    for (int o = 16; o; o >>= 1) ls += __shfl_xor_sync(0xffffffffu, ls, o);
    if (lane == 0) sRed[warp] = ls;
    __syncthreads();
    float gsum = 0.f;
    #pragma unroll
    for (int w = 0; w < 8; ++w) gsum += sRed[w];
    float inv = 1.f / gsum;

    float* prow = g_probs + ((size_t)b*SS + p)*SS;
    for (int i = tid; i < SS; i += 256) prow[i] = sL2[i] * inv;
}

// ---------------- fp16 tensor-core GEMM, 64x64 tile, 256 threads, BK=32, in-block split-K ----------------
// Same proven skeleton as the 381us tf32 kernel, but mma.m16n8k16.f16: per warp per 32-k-tile
// the LDS count halves (2 LDS.128 + 4 LDS.64 feed K=16 instead of K=8) and MMA count halves.
// wg = warp>>2 takes kstep wg (one kstep of 16 per wg). Accumulate fp32.
// A frag (16x16): 4 regs = half2{(lm,lk*2),(lm,lk*2+1)}, {(lm+8,..)}, {(lm,lk*2+8..)}, {(lm+8,lk*2+8..)}
// B frag (16x8):  2 regs = half2{B[lk*2][n],B[lk*2+1][n]}, {B[lk*2+8][n],B[lk*2+9][n]}, n=lm
// MODE 0: plain; 1: relu(+bias); 2: alpha*(+bias). FUSE: A = [ctx | Hj | ctx*Hj].
template<int MODE, bool FUSE>
__global__ void __launch_bounds__(256) gemm_f16(
        const float* __restrict__ A, const float* __restrict__ Bm, float* __restrict__ C,
        int K, int N, size_t strA, size_t strB, size_t strC,
        const float* __restrict__ bias, const float* __restrict__ alphap,
        const float* __restrict__ Ctx, const float* __restrict__ HjP)
{
    A  += (size_t)blockIdx.z * strA;
    Bm += (size_t)blockIdx.z * strB;
    C  += (size_t)blockIdx.z * strC;

    // 16KB: shA[2][1024] | shB[2][1024]; overlaid by 4096-float reduction buffer
    __shared__ __align__(16) unsigned shMem[4096];
    unsigned (*shA)[1024] = (unsigned(*)[1024])shMem;
    unsigned (*shB)[1024] = (unsigned(*)[1024])(shMem + 2048);
    float* sRedu = (float*)shMem;

    int tid = threadIdx.x;
    int lane = tid & 31, warp = tid >> 5;
    int wg = warp >> 2, wsub = warp & 3;
    int warp_m = wsub >> 1, warp_n = wsub & 1;
    int blockM = blockIdx.y * 64, blockN = blockIdx.x * 64;

    float acc[2][4][4];
    #pragma unroll
    for (int mi = 0; mi < 2; ++mi)
        #pragma unroll
        for (int ni = 0; ni < 4; ++ni)
            #pragma unroll
            for (int r = 0; r < 4; ++r) acc[mi][ni][r] = 0.f;

    int lm = lane >> 2, lk = lane & 3;

    // FUSE-aware float2 fetch from virtual X row m at column kg (kg even; never crosses a 768 boundary)
    auto ld2 = [&](int m, int kg, float* dst) {
        if (FUSE) {
            int region = (kg >= 2*HH) ? 2 : ((kg >= HH) ? 1 : 0);
            int kh = kg - region*HH;
            size_t off = (size_t)m*HH + kh;
            if (region == 0) {
                float2 c = *(const float2*)(Ctx + off);
                dst[0] = c.x; dst[1] = c.y;
            } else if (region == 1) {
                float2 h = *(const float2*)(HjP + off);
                dst[0] = h.x; dst[1] = h.y;
            } else {
                float2 c = *(const float2*)(Ctx + off);
                float2 h = *(const float2*)(HjP + off);
                dst[0] = c.x*h.x; dst[1] = c.y*h.y;
            }
        } else {
            float2 v = *(const float2*)(A + (size_t)m*K + kg);
            dst[0] = v.x; dst[1] = v.y;
        }
    };

    // ---- A staging: 8 frag-tiles (ks*4 + mt), one per warp ----
    auto stageA = [&](int kt, float ra[8]) {
        int at = warp;
        int ks = at >> 2, mt = at & 3;
        int m  = blockM + mt*16 + lm;
        int kg = kt + ks*16 + lk*2;
        ld2(m,     kg,     ra + 0);   // a0
        ld2(m + 8, kg,     ra + 2);   // a1
        ld2(m,     kg + 8, ra + 4);   // a2
        ld2(m + 8, kg + 8, ra + 6);   // a3
    };
    auto commitA = [&](const float ra[8], unsigned* dst) {
        uint4 v;
        v.x = pack_h2(ra[0], ra[1]);
        v.y = pack_h2(ra[2], ra[3]);
        v.z = pack_h2(ra[4], ra[5]);
        v.w = pack_h2(ra[6], ra[7]);
        *(uint4*)&dst[warp*128 + lane*4] = v;
    };
    // ---- B staging: 16 frag-tiles (ks*8 + nt), two per warp ----
    auto stageB = [&](int kt, float rb[2][4]) {
        #pragma unroll
        for (int i = 0; i < 2; ++i) {
            int tb = warp*2 + i;
            int ks = tb >> 3, nt = tb & 7;
            int kg = kt + ks*16 + lk*2;
            int n  = blockN + nt*8 + lm;
            const float* p0 = Bm + (size_t)kg*N + n;
            rb[i][0] = p0[0];
            rb[i][1] = p0[(size_t)N];
            rb[i][2] = p0[(size_t)8*N];
            rb[i][3] = p0[(size_t)9*N];
        }
    };
    auto commitB = [&](const float rb[2][4], unsigned* dst) {
        #pragma unroll
        for (int i = 0; i < 2; ++i) {
            int tb = warp*2 + i;
            uint2 v;
            v.x = pack_h2(rb[i][0], rb[i][1]);
            v.y = pack_h2(rb[i][2], rb[i][3]);
            *(uint2*)&dst[tb*64 + lane*2] = v;
        }
    };

    // prologue
    {
        float ra[8], rb[2][4];
        stageA(0, ra); stageB(0, rb);
        commitA(ra, shA[0]); commitB(rb, shB[0]);
    }
    __syncthreads();

    int buf = 0;
    for (int kt = 0; kt < K; kt += 32) {
        float ra[8], rb[2][4];
        bool more = (kt + 32) < K;
        if (more) { stageA(kt + 32, ra); stageB(kt + 32, rb); }

        // this wg computes its single kstep of 16
        {
            int ks = wg;
            unsigned afr[2][4], bfr[4][2];
            #pragma unroll
            for (int mi = 0; mi < 2; ++mi)
                *(uint4*)afr[mi] = *(const uint4*)&shA[buf][(ks*4 + warp_m*2 + mi)*128 + lane*4];
            #pragma unroll
            for (int ni = 0; ni < 4; ++ni)
                *(uint2*)bfr[ni] = *(const uint2*)&shB[buf][(ks*8 + warp_n*4 + ni)*64 + lane*2];
            #pragma unroll
            for (int mi = 0; mi < 2; ++mi)
                #pragma unroll
                for (int ni = 0; ni < 4; ++ni)
                    mma16816(acc[mi][ni], afr[mi], bfr[ni]);
        }

        if (more) { commitA(ra, shA[buf^1]); commitB(rb, shB[buf^1]); }
        __syncthreads();
        buf ^= 1;
    }

    // ---- in-block split-K reduction: wg1 -> smem, wg0 adds + epilogue ----
    if (wg == 1) {
        #pragma unroll
        for (int mi = 0; mi < 2; ++mi)
            #pragma unroll
            for (int ni = 0; ni < 4; ++ni) {
                int t = (wsub*2 + mi)*4 + ni;
                *(float4*)&sRedu[t*128 + lane*4] = *(const float4*)acc[mi][ni];
            }
    }
    __syncthreads();
    if (wg == 0) {
        float al = (MODE == 2) ? *alphap : 1.f;
        #pragma unroll
        for (int mi = 0; mi < 2; ++mi) {
            int r0 = blockM + warp_m*32 + mi*16 + lm;
            #pragma unroll
            for (int ni = 0; ni < 4; ++ni) {
                int t = (wsub*2 + mi)*4 + ni;
                float4 part = *(const float4*)&sRedu[t*128 + lane*4];
                int c0 = blockN + warp_n*32 + ni*8 + lk*2;
                float b0 = 0.f, b1 = 0.f;
                if (MODE != 0) { float2 bv = *(const float2*)(bias + c0); b0 = bv.x; b1 = bv.y; }
                float v0 = acc[mi][ni][0] + part.x + b0;
                float v1 = acc[mi][ni][1] + part.y + b1;
                float v2 = acc[mi][ni][2] + part.z + b0;
                float v3 = acc[mi][ni][3] + part.w + b1;
                if (MODE == 1) {
                    v0 = fmaxf(v0, 0.f); v1 = fmaxf(v1, 0.f);
                    v2 = fmaxf(v2, 0.f); v3 = fmaxf(v3, 0.f);
                }
                if (MODE == 2) { v0 *= al; v1 *= al; v2 *= al; v3 *= al; }
                float2 lo; lo.x = v0; lo.y = v1;
                float2 hi; hi.x = v2; hi.y = v3;
                *(float2*)&C[(size_t)r0*N + c0]       = lo;
                *(float2*)&C[(size_t)(r0 + 8)*N + c0] = hi;
            }
        }
    }
}

// ---------------- launch ----------------
extern "C" void kernel_launch(void* const* d_in, const int* in_sizes, int n_in,
                              void* d_out, int out_size)
{
    const float* Hj   = (const float*)d_in[0];
    const float* Hi   = (const float*)d_in[1];
    const float* Wpj  = (const float*)d_in[2];
    const float* Wpi  = (const float*)d_in[3];
    const float* Ws1  = (const float*)d_in[4];
    const float* bs1  = (const float*)d_in[5];
    const float* ws2  = (const float*)d_in[6];
    const float* bs2  = (const float*)d_in[7];
    const float* Wv1  = (const float*)d_in[8];
    const float* bv1  = (const float*)d_in[9];
    const float* Wv2  = (const float*)d_in[10];
    const float* bv2  = (const float*)d_in[11];
    const float* alph = (const float*)d_in[12];
    const int*   amask= (const int*)d_in[13];
    float* out = (float*)d_out;

    float *pProbs, *pCtx, *pMhid;
    cudaGetSymbolAddress((void**)&pProbs, g_probs);
    cudaGetSymbolAddress((void**)&pCtx,   g_ctx);
    cudaGetSymbolAddress((void**)&pMhid,  g_mhid);

    // K1: projections
    proj_kernel<<<dim3(RR/8, 2), dim3(24, 8)>>>(Hj, Hi, Wpj, Wpi);

    // K2: pairwise scores on tensor cores + softmax
    const size_t smemPW = (size_t)(DD*ZST + 4608 + 2*SS + MM + MM + DD + 32) * sizeof(float);
    cudaFuncSetAttribute(pairwise_kernel, cudaFuncAttributeMaxDynamicSharedMemorySize, (int)smemPW);
    pairwise_kernel<<<dim3(SS, BB), 256, smemPW>>>(Ws1, bs1, ws2, bs2, amask);

    // K3: ctx = probs @ H_i   (per batch: M=512, K=512, N=768)
    gemm_f16<0, false><<<dim3(HH/64, SS/64, BB), 256>>>(
        pProbs, Hi, pCtx, SS, HH,
        (size_t)SS*SS, (size_t)SS*HH, (size_t)SS*HH, nullptr, nullptr, nullptr, nullptr);

    // K4: mhid = relu(X @ Wv1 + bv1), X = [ctx|Hj|ctx*Hj] on the fly (M=2048, K=2304, N=768)
    gemm_f16<1, true><<<dim3(HH/64, RR/64, 1), 256>>>(
        nullptr, Wv1, pMhid, KX, HH, 0, 0, 0, bv1, nullptr, pCtx, Hj);

    // K5: out = alpha * (mhid @ Wv2 + bv2)  (M=2048, K=768, N=768)
    gemm_f16<2, false><<<dim3(HH/64, RR/64, 1), 256>>>(
        pMhid, Wv2, out, HH, HH, 0, 0, 0, bv2, alph, nullptr, nullptr);
}